// round 1
// baseline (speedup 1.0000x reference)
#include <cuda_runtime.h>
#include <math.h>

// Problem constants
#define Bn  2
#define Sn  2048
#define Dn  1024
#define Hn  16
#define HDn 64
#define Mn  (Bn * Sn)   // 4096

// Scratch (static device allocations — allowed; no cudaMalloc anywhere)
__device__ float g_Q[(size_t)Mn * Dn];                    // 16 MB
__device__ float g_K[(size_t)Mn * Dn];                    // 16 MB
__device__ float g_V[(size_t)Mn * Dn];                    // 16 MB
__device__ float g_scores[(size_t)Bn * Hn * Sn * Sn];    // 512 MB (scores -> attn in place)
__device__ float g_attnout[(size_t)Mn * Dn];              // 16 MB

// ---------------------------------------------------------------------------
// Generic NT GEMM: C[m,n] = scale * sum_k A[m,k] * W[n,k] + bias[n]
// Both A and W row-major with K contiguous. 64x64 block tile, BK=16,
// 256 threads, 4x4 per thread. All dims multiples of 64 (no bounds checks).
// ---------------------------------------------------------------------------
__global__ void __launch_bounds__(256) gemm_nt(
    const float* __restrict__ A, int lda,
    const float* __restrict__ W, int ldw,
    const float* __restrict__ bias,
    float* __restrict__ C, int ldc,
    int K, float scale)
{
    __shared__ float As[16][64];
    __shared__ float Ws[16][64];

    const int tid  = threadIdx.x;
    const int tx   = tid & 15;
    const int ty   = tid >> 4;
    const int lrow = tid >> 2;          // 0..63
    const int lk   = (tid & 3) << 2;    // 0,4,8,12

    const float* Ag = A + (size_t)(blockIdx.y * 64 + lrow) * lda + lk;
    const float* Wg = W + (size_t)(blockIdx.x * 64 + lrow) * ldw + lk;

    float acc[4][4] = {};

    for (int k0 = 0; k0 < K; k0 += 16) {
        float4 a4 = *reinterpret_cast<const float4*>(Ag + k0);
        float4 w4 = *reinterpret_cast<const float4*>(Wg + k0);
        As[lk + 0][lrow] = a4.x; As[lk + 1][lrow] = a4.y;
        As[lk + 2][lrow] = a4.z; As[lk + 3][lrow] = a4.w;
        Ws[lk + 0][lrow] = w4.x; Ws[lk + 1][lrow] = w4.y;
        Ws[lk + 2][lrow] = w4.z; Ws[lk + 3][lrow] = w4.w;
        __syncthreads();

        #pragma unroll
        for (int k = 0; k < 16; ++k) {
            float4 av = *reinterpret_cast<const float4*>(&As[k][ty << 2]);
            float4 wv = *reinterpret_cast<const float4*>(&Ws[k][tx << 2]);
            float a[4] = {av.x, av.y, av.z, av.w};
            float w[4] = {wv.x, wv.y, wv.z, wv.w};
            #pragma unroll
            for (int i = 0; i < 4; ++i)
                #pragma unroll
                for (int j = 0; j < 4; ++j)
                    acc[i][j] += a[i] * w[j];
        }
        __syncthreads();
    }

    const int row0 = blockIdx.y * 64 + (ty << 2);
    const int col0 = blockIdx.x * 64 + (tx << 2);
    #pragma unroll
    for (int i = 0; i < 4; ++i) {
        float4 o;
        o.x = acc[i][0] * scale;
        o.y = acc[i][1] * scale;
        o.z = acc[i][2] * scale;
        o.w = acc[i][3] * scale;
        if (bias) {
            o.x += bias[col0 + 0];
            o.y += bias[col0 + 1];
            o.z += bias[col0 + 2];
            o.w += bias[col0 + 3];
        }
        *reinterpret_cast<float4*>(&C[(size_t)(row0 + i) * ldc + col0]) = o;
    }
}

// ---------------------------------------------------------------------------
// Scores: per (b,h): S[q,k] = (1/8) * dot(Q[b,q,h,:], K[b,k,h,:])   (NT, K=64)
// grid = (Sn/64, Sn/64, Bn*Hn)
// ---------------------------------------------------------------------------
__global__ void __launch_bounds__(256) scores_gemm()
{
    __shared__ float As[16][64];
    __shared__ float Bs[16][64];

    const int zb = blockIdx.z;
    const int b  = zb >> 4;
    const int h  = zb & 15;
    const float* A  = g_Q + (size_t)b * Sn * Dn + h * HDn;
    const float* Bm = g_K + (size_t)b * Sn * Dn + h * HDn;
    float*       C  = g_scores + (size_t)zb * Sn * Sn;

    const int tid  = threadIdx.x;
    const int tx   = tid & 15;
    const int ty   = tid >> 4;
    const int lrow = tid >> 2;
    const int lk   = (tid & 3) << 2;

    const float* Ag = A  + (size_t)(blockIdx.y * 64 + lrow) * Dn + lk;
    const float* Bg = Bm + (size_t)(blockIdx.x * 64 + lrow) * Dn + lk;

    float acc[4][4] = {};

    #pragma unroll
    for (int k0 = 0; k0 < HDn; k0 += 16) {
        float4 a4 = *reinterpret_cast<const float4*>(Ag + k0);
        float4 b4 = *reinterpret_cast<const float4*>(Bg + k0);
        As[lk + 0][lrow] = a4.x; As[lk + 1][lrow] = a4.y;
        As[lk + 2][lrow] = a4.z; As[lk + 3][lrow] = a4.w;
        Bs[lk + 0][lrow] = b4.x; Bs[lk + 1][lrow] = b4.y;
        Bs[lk + 2][lrow] = b4.z; Bs[lk + 3][lrow] = b4.w;
        __syncthreads();

        #pragma unroll
        for (int k = 0; k < 16; ++k) {
            float4 av = *reinterpret_cast<const float4*>(&As[k][ty << 2]);
            float4 bv = *reinterpret_cast<const float4*>(&Bs[k][tx << 2]);
            float a[4] = {av.x, av.y, av.z, av.w};
            float w[4] = {bv.x, bv.y, bv.z, bv.w};
            #pragma unroll
            for (int i = 0; i < 4; ++i)
                #pragma unroll
                for (int j = 0; j < 4; ++j)
                    acc[i][j] += a[i] * w[j];
        }
        __syncthreads();
    }

    const int row0 = blockIdx.y * 64 + (ty << 2);
    const int col0 = blockIdx.x * 64 + (tx << 2);
    #pragma unroll
    for (int i = 0; i < 4; ++i) {
        float4 o;
        o.x = acc[i][0] * 0.125f;
        o.y = acc[i][1] * 0.125f;
        o.z = acc[i][2] * 0.125f;
        o.w = acc[i][3] * 0.125f;
        *reinterpret_cast<float4*>(&C[(size_t)(row0 + i) * Sn + col0]) = o;
    }
}

// ---------------------------------------------------------------------------
// Softmax over the HEAD axis (faithful to reference: axis=1).
// For each (b, q, k): attn[h] = exp(s[h]-max) / sum_h exp(s[h]-max), in place.
// ---------------------------------------------------------------------------
__global__ void __launch_bounds__(256) softmax_h()
{
    const size_t SS  = (size_t)Sn * Sn;
    size_t idx = (size_t)blockIdx.x * blockDim.x + threadIdx.x;
    if (idx >= (size_t)Bn * SS) return;
    const size_t b   = idx / SS;
    const size_t rem = idx % SS;           // q*Sn + k
    float* base = g_scores + b * Hn * SS + rem;

    float v[Hn];
    float mx = -1e30f;
    #pragma unroll
    for (int h = 0; h < Hn; ++h) {
        v[h] = base[(size_t)h * SS];
        mx = fmaxf(mx, v[h]);
    }
    float sum = 0.f;
    #pragma unroll
    for (int h = 0; h < Hn; ++h) {
        v[h] = __expf(v[h] - mx);
        sum += v[h];
    }
    const float inv = 1.f / sum;
    #pragma unroll
    for (int h = 0; h < Hn; ++h)
        base[(size_t)h * SS] = v[h] * inv;
}

// ---------------------------------------------------------------------------
// AV: per (b,h): O[q,d] = sum_k attn[q,k] * V[b,k,h,d]   (NN, N=64, K=2048)
// grid = (Sn/64, 1, Bn*Hn)
// ---------------------------------------------------------------------------
__global__ void __launch_bounds__(256) av_gemm()
{
    __shared__ float As[16][64];
    __shared__ float Bs[16][64];

    const int zb = blockIdx.z;
    const int b  = zb >> 4;
    const int h  = zb & 15;
    const float* A  = g_scores + (size_t)zb * Sn * Sn;          // attn, lda = Sn
    const float* Bm = g_V + (size_t)b * Sn * Dn + h * HDn;      // ldb = Dn
    float*       C  = g_attnout + (size_t)b * Sn * Dn + h * HDn; // ldc = Dn

    const int tid  = threadIdx.x;
    const int tx   = tid & 15;
    const int ty   = tid >> 4;
    const int lrow = tid >> 2;          // A-load row within tile
    const int lk   = (tid & 3) << 2;    // A-load k offset
    const int bk   = tid >> 4;          // B-load k row (0..15)
    const int bn   = (tid & 15) << 2;   // B-load n offset

    const float* Ag = A + (size_t)(blockIdx.x * 64 + lrow) * Sn + lk;

    float acc[4][4] = {};

    for (int k0 = 0; k0 < Sn; k0 += 16) {
        float4 a4 = *reinterpret_cast<const float4*>(Ag + k0);
        float4 b4 = *reinterpret_cast<const float4*>(Bm + (size_t)(k0 + bk) * Dn + bn);
        As[lk + 0][lrow] = a4.x; As[lk + 1][lrow] = a4.y;
        As[lk + 2][lrow] = a4.z; As[lk + 3][lrow] = a4.w;
        *reinterpret_cast<float4*>(&Bs[bk][bn]) = b4;
        __syncthreads();

        #pragma unroll
        for (int k = 0; k < 16; ++k) {
            float4 av = *reinterpret_cast<const float4*>(&As[k][ty << 2]);
            float4 bv = *reinterpret_cast<const float4*>(&Bs[k][tx << 2]);
            float a[4] = {av.x, av.y, av.z, av.w};
            float w[4] = {bv.x, bv.y, bv.z, bv.w};
            #pragma unroll
            for (int i = 0; i < 4; ++i)
                #pragma unroll
                for (int j = 0; j < 4; ++j)
                    acc[i][j] += a[i] * w[j];
        }
        __syncthreads();
    }

    const int row0 = blockIdx.x * 64 + (ty << 2);
    const int col0 = tx << 2;
    #pragma unroll
    for (int i = 0; i < 4; ++i) {
        float4 o;
        o.x = acc[i][0]; o.y = acc[i][1]; o.z = acc[i][2]; o.w = acc[i][3];
        *reinterpret_cast<float4*>(&C[(size_t)(row0 + i) * Dn + col0]) = o;
    }
}

// ---------------------------------------------------------------------------
extern "C" void kernel_launch(void* const* d_in, const int* in_sizes, int n_in,
                              void* d_out, int out_size)
{
    const float* x  = (const float*)d_in[0];
    const float* Wq = (const float*)d_in[1];
    const float* bq = (const float*)d_in[2];
    const float* Wk = (const float*)d_in[3];
    const float* bk = (const float*)d_in[4];
    const float* Wv = (const float*)d_in[5];
    const float* bv = (const float*)d_in[6];
    const float* Wo = (const float*)d_in[7];
    const float* bo = (const float*)d_in[8];
    float* out = (float*)d_out;

    float *Qp, *Kp, *Vp, *AOp;
    cudaGetSymbolAddress((void**)&Qp,  g_Q);
    cudaGetSymbolAddress((void**)&Kp,  g_K);
    cudaGetSymbolAddress((void**)&Vp,  g_V);
    cudaGetSymbolAddress((void**)&AOp, g_attnout);

    dim3 gproj(Dn / 64, Mn / 64);   // (16, 64)

    // QKV projections
    gemm_nt<<<gproj, 256>>>(x, Dn, Wq, Dn, bq, Qp, Dn, Dn, 1.0f);
    gemm_nt<<<gproj, 256>>>(x, Dn, Wk, Dn, bk, Kp, Dn, Dn, 1.0f);
    gemm_nt<<<gproj, 256>>>(x, Dn, Wv, Dn, bv, Vp, Dn, Dn, 1.0f);

    // Scores (per b,h)
    dim3 gs(Sn / 64, Sn / 64, Bn * Hn);
    scores_gemm<<<gs, 256>>>();

    // Softmax over head axis
    const size_t tot = (size_t)Bn * Sn * Sn;
    softmax_h<<<(unsigned)((tot + 255) / 256), 256>>>();

    // attn @ V
    dim3 gav(Sn / 64, 1, Bn * Hn);
    av_gemm<<<gav, 256>>>();

    // Output projection
    gemm_nt<<<gproj, 256>>>(AOp, Dn, Wo, Dn, bo, out, Dn, Dn, 1.0f);
}

// round 3
// speedup vs baseline: 1.9008x; 1.9008x over previous
#include <cuda_runtime.h>
#include <math.h>
#include <stdint.h>

// Problem constants
#define Bn  2
#define Sn  2048
#define Dn  1024
#define Hn  16
#define HDn 64
#define Mn  (Bn * Sn)   // 4096

// Scratch (static device allocations — no cudaMalloc anywhere)
__device__ float g_Q[(size_t)Mn * Dn];                    // 16 MB
__device__ float g_K[(size_t)Mn * Dn];                    // 16 MB
__device__ float g_V[(size_t)Mn * Dn];                    // 16 MB
__device__ float g_scores[(size_t)Bn * Hn * Sn * Sn];     // 512 MB (scores -> attn in place)
__device__ float g_attnout[(size_t)Mn * Dn];              // 16 MB

// ---------------------------------------------------------------------------
// tf32 helpers
// ---------------------------------------------------------------------------
__device__ __forceinline__ uint32_t f2tf(float x) {
    uint32_t u;
    asm("cvt.rna.tf32.f32 %0, %1;" : "=r"(u) : "f"(x));
    return u;
}

__device__ __forceinline__ void mma_tf32(float* c, const uint32_t* a, const uint32_t* b) {
    asm volatile(
        "mma.sync.aligned.m16n8k8.row.col.f32.tf32.tf32.f32 "
        "{%0,%1,%2,%3}, {%4,%5,%6,%7}, {%8,%9}, {%0,%1,%2,%3};\n"
        : "+f"(c[0]), "+f"(c[1]), "+f"(c[2]), "+f"(c[3])
        : "r"(a[0]), "r"(a[1]), "r"(a[2]), "r"(a[3]), "r"(b[0]), "r"(b[1]));
}

// ---------------------------------------------------------------------------
// NT GEMM core (tensor cores, tf32): C[m,n] = scale * sum_k A[m,k]*W[n,k] + bias
// Block tile 128x128, BK=32, 256 threads (8 warps, 4x2), warp tile 32x64.
// Smem pad 36 floats/row -> conflict-free fragment loads.
// ---------------------------------------------------------------------------
__device__ __forceinline__ void gemm_nt_core(
    const float* __restrict__ A, int lda,
    const float* __restrict__ W, int ldw,
    const float* __restrict__ bias,
    float* __restrict__ C, int ldc,
    int K, float scale, int bm, int bn)
{
    __shared__ uint32_t As[128 * 36];
    __shared__ uint32_t Ws[128 * 36];

    const int tid  = threadIdx.x;
    const int lane = tid & 31;
    const int warp = tid >> 5;
    const int grp  = lane >> 2;   // 0..7
    const int tig  = lane & 3;    // 0..3
    const int wm   = (warp & 3) * 32;
    const int wn   = (warp >> 2) * 64;
    const int lrow = tid >> 1;          // 0..127
    const int lkb  = (tid & 1) * 16;    // 0 or 16

    float acc[2][8][4] = {};

    for (int k0 = 0; k0 < K; k0 += 32) {
        const float* Ap = A + (size_t)(bm + lrow) * lda + k0 + lkb;
        const float* Wp = W + (size_t)(bn + lrow) * ldw + k0 + lkb;
        #pragma unroll
        for (int i = 0; i < 4; ++i) {
            float4 v = *reinterpret_cast<const float4*>(Ap + 4 * i);
            uint32_t* d = &As[lrow * 36 + lkb + 4 * i];
            d[0] = f2tf(v.x); d[1] = f2tf(v.y); d[2] = f2tf(v.z); d[3] = f2tf(v.w);
            float4 w = *reinterpret_cast<const float4*>(Wp + 4 * i);
            uint32_t* e = &Ws[lrow * 36 + lkb + 4 * i];
            e[0] = f2tf(w.x); e[1] = f2tf(w.y); e[2] = f2tf(w.z); e[3] = f2tf(w.w);
        }
        __syncthreads();

        #pragma unroll
        for (int ks = 0; ks < 4; ++ks) {
            uint32_t a[2][4], b[8][2];
            #pragma unroll
            for (int mi = 0; mi < 2; ++mi) {
                int r = wm + mi * 16 + grp;
                a[mi][0] = As[r * 36 + ks * 8 + tig];
                a[mi][1] = As[(r + 8) * 36 + ks * 8 + tig];
                a[mi][2] = As[r * 36 + ks * 8 + tig + 4];
                a[mi][3] = As[(r + 8) * 36 + ks * 8 + tig + 4];
            }
            #pragma unroll
            for (int ni = 0; ni < 8; ++ni) {
                int n = wn + ni * 8 + grp;
                b[ni][0] = Ws[n * 36 + ks * 8 + tig];
                b[ni][1] = Ws[n * 36 + ks * 8 + tig + 4];
            }
            #pragma unroll
            for (int mi = 0; mi < 2; ++mi)
                #pragma unroll
                for (int ni = 0; ni < 8; ++ni)
                    mma_tf32(acc[mi][ni], a[mi], b[ni]);
        }
        __syncthreads();
    }

    #pragma unroll
    for (int mi = 0; mi < 2; ++mi) {
        int r0 = bm + wm + mi * 16 + grp;
        #pragma unroll
        for (int ni = 0; ni < 8; ++ni) {
            int c0 = bn + wn + ni * 8 + 2 * tig;
            float bx = 0.f, by = 0.f;
            if (bias) { bx = bias[c0]; by = bias[c0 + 1]; }
            float2 v0 = make_float2(acc[mi][ni][0] * scale + bx,
                                    acc[mi][ni][1] * scale + by);
            float2 v1 = make_float2(acc[mi][ni][2] * scale + bx,
                                    acc[mi][ni][3] * scale + by);
            *reinterpret_cast<float2*>(&C[(size_t)r0 * ldc + c0]) = v0;
            *reinterpret_cast<float2*>(&C[(size_t)(r0 + 8) * ldc + c0]) = v1;
        }
    }
}

// Projection-style GEMM: grid (N/128, M/128)
__global__ void __launch_bounds__(256) proj_tf32(
    const float* __restrict__ A, int lda,
    const float* __restrict__ W, int ldw,
    const float* __restrict__ bias,
    float* __restrict__ C, int ldc,
    int K, float scale)
{
    gemm_nt_core(A, lda, W, ldw, bias, C, ldc, K, scale,
                 blockIdx.y * 128, blockIdx.x * 128);
}

// Scores: per (b,h): S[q,k] = 0.125 * dot(Q_h[q,:], K_h[k,:]), K=64
// grid (Sn/128, Sn/128, Bn*Hn)
__global__ void __launch_bounds__(256) scores_tf32()
{
    const int zb = blockIdx.z;
    const int b  = zb >> 4;
    const int h  = zb & 15;
    const float* A  = g_Q + (size_t)b * Sn * Dn + h * HDn;
    const float* Bm = g_K + (size_t)b * Sn * Dn + h * HDn;
    float*       C  = g_scores + (size_t)zb * Sn * Sn;
    gemm_nt_core(A, Dn, Bm, Dn, nullptr, C, Sn, HDn, 0.125f,
                 blockIdx.y * 128, blockIdx.x * 128);
}

// ---------------------------------------------------------------------------
// Softmax over HEAD axis (axis=1, faithful to reference), in place.
// ---------------------------------------------------------------------------
__global__ void __launch_bounds__(256) softmax_h()
{
    const size_t SS = (size_t)Sn * Sn;
    size_t idx = (size_t)blockIdx.x * blockDim.x + threadIdx.x;
    if (idx >= (size_t)Bn * SS) return;
    const size_t b   = idx / SS;
    const size_t rem = idx % SS;
    float* base = g_scores + b * Hn * SS + rem;

    float v[Hn];
    float mx = -1e30f;
    #pragma unroll
    for (int h = 0; h < Hn; ++h) {
        v[h] = base[(size_t)h * SS];
        mx = fmaxf(mx, v[h]);
    }
    float sum = 0.f;
    #pragma unroll
    for (int h = 0; h < Hn; ++h) {
        v[h] = __expf(v[h] - mx);
        sum += v[h];
    }
    const float inv = 1.f / sum;
    #pragma unroll
    for (int h = 0; h < Hn; ++h)
        base[(size_t)h * SS] = v[h] * inv;
}

// ---------------------------------------------------------------------------
// AV (NN GEMM, tensor cores): per (b,h): O[q,d] = sum_k attn[q,k] * V[k, h*64+d]
// Block tile 128(q) x 64(d), BK=32, 256 threads (8 warps stacked along m).
// V tile stored TRANSPOSED in smem: Vs[d][k], stride 33 -> conflict-free
// fragment reads identical to the NT-core pattern.
// grid (Sn/128, 1, Bn*Hn)
// ---------------------------------------------------------------------------
__global__ void __launch_bounds__(256) av_tf32()
{
    __shared__ uint32_t As[128 * 36];
    __shared__ uint32_t Vs[64 * 33];   // [d (0..63)][k (0..31)]

    const int zb = blockIdx.z;
    const int b  = zb >> 4;
    const int h  = zb & 15;
    const float* A = g_scores  + (size_t)zb * Sn * Sn;           // lda = Sn
    const float* V = g_V       + (size_t)b * Sn * Dn + h * HDn;  // ldv = Dn
    float*       C = g_attnout + (size_t)b * Sn * Dn + h * HDn;  // ldc = Dn

    const int tid  = threadIdx.x;
    const int lane = tid & 31;
    const int warp = tid >> 5;
    const int grp  = lane >> 2;
    const int tig  = lane & 3;
    const int wm   = warp * 16;
    const int bm   = blockIdx.x * 128;
    const int lrow = tid >> 1;
    const int lkb  = (tid & 1) * 16;
    const int vk   = tid >> 3;          // 0..31 (k row within tile)
    const int vn   = (tid & 7) * 8;     // 0..56 (d offset)

    float acc[8][4] = {};

    for (int k0 = 0; k0 < Sn; k0 += 32) {
        const float* Ap = A + (size_t)(bm + lrow) * Sn + k0 + lkb;
        #pragma unroll
        for (int i = 0; i < 4; ++i) {
            float4 v = *reinterpret_cast<const float4*>(Ap + 4 * i);
            uint32_t* d = &As[lrow * 36 + lkb + 4 * i];
            d[0] = f2tf(v.x); d[1] = f2tf(v.y); d[2] = f2tf(v.z); d[3] = f2tf(v.w);
        }
        // V tile: load 8 d-values of row k0+vk, store transposed Vs[d][k]
        #pragma unroll
        for (int i = 0; i < 2; ++i) {
            float4 v = *reinterpret_cast<const float4*>(
                V + (size_t)(k0 + vk) * Dn + vn + 4 * i);
            Vs[(vn + 4 * i + 0) * 33 + vk] = f2tf(v.x);
            Vs[(vn + 4 * i + 1) * 33 + vk] = f2tf(v.y);
            Vs[(vn + 4 * i + 2) * 33 + vk] = f2tf(v.z);
            Vs[(vn + 4 * i + 3) * 33 + vk] = f2tf(v.w);
        }
        __syncthreads();

        #pragma unroll
        for (int ks = 0; ks < 4; ++ks) {
            uint32_t a[4], bfr[8][2];
            {
                int r = wm + grp;
                a[0] = As[r * 36 + ks * 8 + tig];
                a[1] = As[(r + 8) * 36 + ks * 8 + tig];
                a[2] = As[r * 36 + ks * 8 + tig + 4];
                a[3] = As[(r + 8) * 36 + ks * 8 + tig + 4];
            }
            #pragma unroll
            for (int ni = 0; ni < 8; ++ni) {
                bfr[ni][0] = Vs[(ni * 8 + grp) * 33 + ks * 8 + tig];
                bfr[ni][1] = Vs[(ni * 8 + grp) * 33 + ks * 8 + tig + 4];
            }
            #pragma unroll
            for (int ni = 0; ni < 8; ++ni)
                mma_tf32(acc[ni], a, bfr[ni]);
        }
        __syncthreads();
    }

    const int r0 = bm + wm + grp;
    #pragma unroll
    for (int ni = 0; ni < 8; ++ni) {
        int c0 = ni * 8 + 2 * tig;
        float2 v0 = make_float2(acc[ni][0], acc[ni][1]);
        float2 v1 = make_float2(acc[ni][2], acc[ni][3]);
        *reinterpret_cast<float2*>(&C[(size_t)r0 * Dn + c0]) = v0;
        *reinterpret_cast<float2*>(&C[(size_t)(r0 + 8) * Dn + c0]) = v1;
    }
}

// ---------------------------------------------------------------------------
extern "C" void kernel_launch(void* const* d_in, const int* in_sizes, int n_in,
                              void* d_out, int out_size)
{
    const float* x  = (const float*)d_in[0];
    const float* Wq = (const float*)d_in[1];
    const float* bq = (const float*)d_in[2];
    const float* Wk = (const float*)d_in[3];
    const float* bk = (const float*)d_in[4];
    const float* Wv = (const float*)d_in[5];
    const float* bv = (const float*)d_in[6];
    const float* Wo = (const float*)d_in[7];
    const float* bo = (const float*)d_in[8];
    float* out = (float*)d_out;

    float *Qp, *Kp, *Vp, *AOp;
    cudaGetSymbolAddress((void**)&Qp,  g_Q);
    cudaGetSymbolAddress((void**)&Kp,  g_K);
    cudaGetSymbolAddress((void**)&Vp,  g_V);
    cudaGetSymbolAddress((void**)&AOp, g_attnout);

    dim3 gproj(Dn / 128, Mn / 128);   // (8, 32)

    // QKV projections
    proj_tf32<<<gproj, 256>>>(x, Dn, Wq, Dn, bq, Qp, Dn, Dn, 1.0f);
    proj_tf32<<<gproj, 256>>>(x, Dn, Wk, Dn, bk, Kp, Dn, Dn, 1.0f);
    proj_tf32<<<gproj, 256>>>(x, Dn, Wv, Dn, bv, Vp, Dn, Dn, 1.0f);

    // Scores (per b,h)
    dim3 gs(Sn / 128, Sn / 128, Bn * Hn);
    scores_tf32<<<gs, 256>>>();

    // Softmax over head axis
    const size_t tot = (size_t)Bn * Sn * Sn;
    softmax_h<<<(unsigned)((tot + 255) / 256), 256>>>();

    // attn @ V
    dim3 gav(Sn / 128, 1, Bn * Hn);
    av_tf32<<<gav, 256>>>();

    // Output projection
    proj_tf32<<<gproj, 256>>>(AOp, Dn, Wo, Dn, bo, out, Dn, Dn, 1.0f);
}

// round 4
// speedup vs baseline: 4.6395x; 2.4409x over previous
#include <cuda_runtime.h>
#include <cuda_fp16.h>
#include <math.h>
#include <stdint.h>

// Problem constants
#define Bn  2
#define Sn  2048
#define Dn  1024
#define Hn  16
#define HDn 64
#define Mn  (Bn * Sn)   // 4096

// Scratch (static device allocations — no cudaMalloc anywhere)
__device__ __half g_xh[(size_t)Mn * Dn];           // 8 MB  x in fp16
__device__ __half g_Wh[4][(size_t)Dn * Dn];        // 8 MB  Wq,Wk,Wv,Wo fp16
__device__ __half g_Qh[(size_t)Mn * Dn];           // 8 MB
__device__ __half g_Kh[(size_t)Mn * Dn];           // 8 MB
__device__ __half g_Vh[(size_t)Mn * Dn];           // 8 MB
__device__ __half g_Vt[(size_t)Bn * Dn * Sn];      // 8 MB  V transposed [b][d][tok]
__device__ float  g_scores[(size_t)Bn * Hn * Sn * Sn];  // 512 MB fp32 raw scores
__device__ __half g_P[(size_t)Bn * Hn * Sn * Sn];       // 256 MB fp16 probs
__device__ __half g_AOh[(size_t)Mn * Dn];          // 8 MB

// ---------------------------------------------------------------------------
// PTX helpers
// ---------------------------------------------------------------------------
__device__ __forceinline__ uint32_t smem_u32(const void* p) {
    return (uint32_t)__cvta_generic_to_shared(p);
}
__device__ __forceinline__ void cp16(uint32_t dst, const void* src) {
    asm volatile("cp.async.cg.shared.global [%0], [%1], 16;\n" :: "r"(dst), "l"(src));
}
__device__ __forceinline__ void cp_commit() { asm volatile("cp.async.commit_group;\n"); }
__device__ __forceinline__ void cp_wait0()  { asm volatile("cp.async.wait_group 0;\n"); }

__device__ __forceinline__ void ldsm4(uint32_t& r0, uint32_t& r1, uint32_t& r2, uint32_t& r3,
                                      uint32_t addr) {
    asm volatile("ldmatrix.sync.aligned.m8n8.x4.shared.b16 {%0,%1,%2,%3}, [%4];\n"
                 : "=r"(r0), "=r"(r1), "=r"(r2), "=r"(r3) : "r"(addr));
}
__device__ __forceinline__ void mma16816(float* c,
                                         uint32_t a0, uint32_t a1, uint32_t a2, uint32_t a3,
                                         uint32_t b0, uint32_t b1) {
    asm volatile(
        "mma.sync.aligned.m16n8k16.row.col.f32.f16.f16.f32 "
        "{%0,%1,%2,%3},{%4,%5,%6,%7},{%8,%9},{%0,%1,%2,%3};\n"
        : "+f"(c[0]), "+f"(c[1]), "+f"(c[2]), "+f"(c[3])
        : "r"(a0), "r"(a1), "r"(a2), "r"(a3), "r"(b0), "r"(b1));
}

// Swizzled byte offset inside an 8KB (128-row) or 4KB (64-row) tile:
// row stride 64B = 4 chunks of 16B. phys_chunk = c ^ (row&3) ^ ((row>>2)&1)
// -> ldmatrix 8-row groups hit 32 distinct banks.
__device__ __forceinline__ uint32_t sw_off(int row, int chunk) {
    return ((uint32_t)row << 6) + ((uint32_t)((chunk ^ (row & 3) ^ ((row >> 2) & 1))) << 4);
}

// ---------------------------------------------------------------------------
// fp16 NT GEMM core: C[m,n] = scale * sum_k A[m,k]*W[n,k] (+ bias[n])
// Block 128x128, BK=32, 256 thr (8 warps 4x2), warp tile 32x64, m16n8k16,
// cp.async double-buffered, swizzled smem, ldmatrix fragments.
// ---------------------------------------------------------------------------
template <bool OUT_HALF>
__device__ __forceinline__ void gemm_nt_f16(
    const __half* __restrict__ A, int lda,
    const __half* __restrict__ W, int ldw,
    const float* __restrict__ bias,
    void* __restrict__ Cv, int ldc,
    int K, float scale, int bm, int bn)
{
    __shared__ __align__(16) char As[2][8192];
    __shared__ __align__(16) char Ws[2][8192];

    const int tid  = threadIdx.x;
    const int lane = tid & 31;
    const int warp = tid >> 5;
    const int grp  = lane >> 2;
    const int tig  = lane & 3;
    const int wm   = (warp & 3) * 32;
    const int wn   = (warp >> 2) * 64;
    const int lrow = tid >> 1;
    const int lc2  = (tid & 1) * 2;

    uint32_t asb[2] = { smem_u32(As[0]), smem_u32(As[1]) };
    uint32_t wsb[2] = { smem_u32(Ws[0]), smem_u32(Ws[1]) };

    const __half* Ag = A + (size_t)(bm + lrow) * lda;
    const __half* Wg = W + (size_t)(bn + lrow) * ldw;

    float acc[2][8][4] = {};

    const int nIter = K >> 5;
    // prologue: load iter 0 into buf 0
    cp16(asb[0] + sw_off(lrow, lc2),     Ag + lc2 * 8);
    cp16(asb[0] + sw_off(lrow, lc2 + 1), Ag + lc2 * 8 + 8);
    cp16(wsb[0] + sw_off(lrow, lc2),     Wg + lc2 * 8);
    cp16(wsb[0] + sw_off(lrow, lc2 + 1), Wg + lc2 * 8 + 8);
    cp_commit();

    for (int it = 0; it < nIter; ++it) {
        const int buf = it & 1;
        cp_wait0();
        __syncthreads();
        if (it + 1 < nIter) {
            const int k0 = (it + 1) << 5;
            cp16(asb[buf ^ 1] + sw_off(lrow, lc2),     Ag + k0 + lc2 * 8);
            cp16(asb[buf ^ 1] + sw_off(lrow, lc2 + 1), Ag + k0 + lc2 * 8 + 8);
            cp16(wsb[buf ^ 1] + sw_off(lrow, lc2),     Wg + k0 + lc2 * 8);
            cp16(wsb[buf ^ 1] + sw_off(lrow, lc2 + 1), Wg + k0 + lc2 * 8 + 8);
            cp_commit();
        }
        #pragma unroll
        for (int ks = 0; ks < 2; ++ks) {
            const int frow = (lane & 7) + ((lane >> 3) & 1) * 8;
            const int fch  = ks * 2 + (lane >> 4);
            uint32_t a[2][4];
            #pragma unroll
            for (int mi = 0; mi < 2; ++mi)
                ldsm4(a[mi][0], a[mi][1], a[mi][2], a[mi][3],
                      asb[buf] + sw_off(wm + mi * 16 + frow, fch));
            uint32_t b[8][2];
            #pragma unroll
            for (int nj = 0; nj < 4; ++nj) {
                uint32_t r0, r1, r2, r3;
                ldsm4(r0, r1, r2, r3, wsb[buf] + sw_off(wn + nj * 16 + frow, fch));
                b[nj * 2][0] = r0;  b[nj * 2][1] = r2;
                b[nj * 2 + 1][0] = r1;  b[nj * 2 + 1][1] = r3;
            }
            #pragma unroll
            for (int mi = 0; mi < 2; ++mi)
                #pragma unroll
                for (int ni = 0; ni < 8; ++ni)
                    mma16816(acc[mi][ni], a[mi][0], a[mi][1], a[mi][2], a[mi][3],
                             b[ni][0], b[ni][1]);
        }
    }

    #pragma unroll
    for (int mi = 0; mi < 2; ++mi) {
        const int r0 = bm + wm + mi * 16 + grp;
        #pragma unroll
        for (int ni = 0; ni < 8; ++ni) {
            const int c0 = bn + wn + ni * 8 + 2 * tig;
            float bx = 0.f, by = 0.f;
            if (bias) { bx = bias[c0]; by = bias[c0 + 1]; }
            const float x0 = acc[mi][ni][0] * scale + bx;
            const float y0 = acc[mi][ni][1] * scale + by;
            const float x1 = acc[mi][ni][2] * scale + bx;
            const float y1 = acc[mi][ni][3] * scale + by;
            if (OUT_HALF) {
                __half* C = (__half*)Cv;
                *(__half2*)&C[(size_t)r0 * ldc + c0]       = __floats2half2_rn(x0, y0);
                *(__half2*)&C[(size_t)(r0 + 8) * ldc + c0] = __floats2half2_rn(x1, y1);
            } else {
                float* C = (float*)Cv;
                *(float2*)&C[(size_t)r0 * ldc + c0]       = make_float2(x0, y0);
                *(float2*)&C[(size_t)(r0 + 8) * ldc + c0] = make_float2(x1, y1);
            }
        }
    }
}

// Projection: out fp16
__global__ void __launch_bounds__(256) proj_h(
    const __half* __restrict__ A, const __half* __restrict__ W,
    const float* __restrict__ bias, __half* __restrict__ C)
{
    gemm_nt_f16<true>(A, Dn, W, Dn, bias, C, Dn, Dn, 1.0f,
                      blockIdx.y * 128, blockIdx.x * 128);
}

// Final projection: out fp32
__global__ void __launch_bounds__(256) proj_f(
    const __half* __restrict__ A, const __half* __restrict__ W,
    const float* __restrict__ bias, float* __restrict__ C)
{
    gemm_nt_f16<false>(A, Dn, W, Dn, bias, C, Dn, Dn, 1.0f,
                       blockIdx.y * 128, blockIdx.x * 128);
}

// Scores: per (b,h): S[q,k] = 0.125 * dot(Q_h[q,:], K_h[k,:]); fp32 out
__global__ void __launch_bounds__(256) scores_h()
{
    const int zb = blockIdx.z;
    const int b  = zb >> 4;
    const int h  = zb & 15;
    const __half* A = g_Qh + (size_t)b * Sn * Dn + h * HDn;
    const __half* W = g_Kh + (size_t)b * Sn * Dn + h * HDn;
    float* C = g_scores + (size_t)zb * Sn * Sn;
    gemm_nt_f16<false>(A, Dn, W, Dn, nullptr, C, Sn, HDn, 0.125f,
                       blockIdx.y * 128, blockIdx.x * 128);
}

// ---------------------------------------------------------------------------
// Softmax over HEAD axis (axis=1, faithful): fp32 scores -> fp16 probs
// ---------------------------------------------------------------------------
__global__ void __launch_bounds__(256) softmax_h16()
{
    const size_t SS = (size_t)Sn * Sn;
    const size_t idx = (size_t)blockIdx.x * 256 + threadIdx.x;
    const size_t b   = idx / SS;
    const size_t rem = idx % SS;
    const float* sbase = g_scores + b * Hn * SS + rem;
    __half* pbase = g_P + b * Hn * SS + rem;

    float v[Hn];
    float mx = -1e30f;
    #pragma unroll
    for (int h = 0; h < Hn; ++h) {
        v[h] = sbase[(size_t)h * SS];
        mx = fmaxf(mx, v[h]);
    }
    float sum = 0.f;
    #pragma unroll
    for (int h = 0; h < Hn; ++h) {
        v[h] = __expf(v[h] - mx);
        sum += v[h];
    }
    const float inv = 1.f / sum;
    #pragma unroll
    for (int h = 0; h < Hn; ++h)
        pbase[(size_t)h * SS] = __float2half(v[h] * inv);
}

// ---------------------------------------------------------------------------
// Transpose Vh[b*S + tok][d] -> Vt[b][d][tok] (fp16), 64x64 tiles
// ---------------------------------------------------------------------------
__global__ void __launch_bounds__(256) transpose_v()
{
    __shared__ __half ts[64][72];
    const int t0 = blockIdx.x * 64;
    const int d0 = blockIdx.y * 64;
    const int b  = blockIdx.z;
    const int tid = threadIdx.x;

    const __half* src = g_Vh + ((size_t)b * Sn + t0) * Dn + d0;
    const int r = tid >> 2, c2 = (tid & 3) * 2;
    *(uint4*)&ts[r][c2 * 8]     = *(const uint4*)(src + (size_t)r * Dn + c2 * 8);
    *(uint4*)&ts[r][c2 * 8 + 8] = *(const uint4*)(src + (size_t)r * Dn + c2 * 8 + 8);
    __syncthreads();

    const int dl = tid >> 2, seg = tid & 3;
    __half tmp[16];
    #pragma unroll
    for (int j = 0; j < 16; ++j) tmp[j] = ts[seg * 16 + j][dl];
    __half* dst = g_Vt + ((size_t)b * Dn + d0 + dl) * Sn + t0 + seg * 16;
    *(uint4*)dst       = *(uint4*)tmp;
    *(uint4*)(dst + 8) = *(uint4*)(tmp + 8);
}

// ---------------------------------------------------------------------------
// AV: per (b,h): O[q,d] = sum_k P_h[q,k] * Vt_h[d,k]  (NT, N=64)
// Block 128q x 64d, BK=32, 8 warps stacked on m. grid (S/128, 1, B*H)
// ---------------------------------------------------------------------------
__global__ void __launch_bounds__(256) av_h()
{
    __shared__ __align__(16) char Ps[2][8192];
    __shared__ __align__(16) char Vs[2][4096];

    const int zb = blockIdx.z;
    const int b  = zb >> 4;
    const int h  = zb & 15;
    const __half* P  = g_P + (size_t)zb * Sn * Sn;
    const __half* Vt = g_Vt + ((size_t)b * Dn + h * HDn) * Sn;
    __half* C = g_AOh + (size_t)b * Sn * Dn + h * HDn;

    const int tid  = threadIdx.x;
    const int lane = tid & 31;
    const int warp = tid >> 5;
    const int grp  = lane >> 2;
    const int tig  = lane & 3;
    const int bm   = blockIdx.x * 128;
    const int wm   = warp * 16;
    const int prow = tid >> 1, pc2 = (tid & 1) * 2;
    const int vrow = tid >> 2, vc  = tid & 3;

    uint32_t psb[2] = { smem_u32(Ps[0]), smem_u32(Ps[1]) };
    uint32_t vsb[2] = { smem_u32(Vs[0]), smem_u32(Vs[1]) };

    const __half* Pg = P  + (size_t)(bm + prow) * Sn;
    const __half* Vg = Vt + (size_t)vrow * Sn;

    float acc[8][4] = {};

    // prologue
    cp16(psb[0] + sw_off(prow, pc2),     Pg + pc2 * 8);
    cp16(psb[0] + sw_off(prow, pc2 + 1), Pg + pc2 * 8 + 8);
    cp16(vsb[0] + sw_off(vrow, vc),      Vg + vc * 8);
    cp_commit();

    const int nIter = Sn >> 5;   // 64
    for (int it = 0; it < nIter; ++it) {
        const int buf = it & 1;
        cp_wait0();
        __syncthreads();
        if (it + 1 < nIter) {
            const int k0 = (it + 1) << 5;
            cp16(psb[buf ^ 1] + sw_off(prow, pc2),     Pg + k0 + pc2 * 8);
            cp16(psb[buf ^ 1] + sw_off(prow, pc2 + 1), Pg + k0 + pc2 * 8 + 8);
            cp16(vsb[buf ^ 1] + sw_off(vrow, vc),      Vg + k0 + vc * 8);
            cp_commit();
        }
        #pragma unroll
        for (int ks = 0; ks < 2; ++ks) {
            const int frow = (lane & 7) + ((lane >> 3) & 1) * 8;
            const int fch  = ks * 2 + (lane >> 4);
            uint32_t a[4];
            ldsm4(a[0], a[1], a[2], a[3], psb[buf] + sw_off(wm + frow, fch));
            uint32_t bfr[8][2];
            #pragma unroll
            for (int nj = 0; nj < 4; ++nj) {
                uint32_t r0, r1, r2, r3;
                ldsm4(r0, r1, r2, r3, vsb[buf] + sw_off(nj * 16 + frow, fch));
                bfr[nj * 2][0] = r0;  bfr[nj * 2][1] = r2;
                bfr[nj * 2 + 1][0] = r1;  bfr[nj * 2 + 1][1] = r3;
            }
            #pragma unroll
            for (int ni = 0; ni < 8; ++ni)
                mma16816(acc[ni], a[0], a[1], a[2], a[3], bfr[ni][0], bfr[ni][1]);
        }
    }

    const int r0 = bm + wm + grp;
    #pragma unroll
    for (int ni = 0; ni < 8; ++ni) {
        const int c0 = ni * 8 + 2 * tig;
        *(__half2*)&C[(size_t)r0 * Dn + c0]       = __floats2half2_rn(acc[ni][0], acc[ni][1]);
        *(__half2*)&C[(size_t)(r0 + 8) * Dn + c0] = __floats2half2_rn(acc[ni][2], acc[ni][3]);
    }
}

// ---------------------------------------------------------------------------
// fp32 -> fp16 conversion (n multiple of 8, exact grid)
// ---------------------------------------------------------------------------
__global__ void __launch_bounds__(256) f32_to_f16(
    const float* __restrict__ s, __half* __restrict__ d)
{
    const size_t i = ((size_t)blockIdx.x * 256 + threadIdx.x) * 8;
    float4 a = *(const float4*)(s + i);
    float4 b = *(const float4*)(s + i + 4);
    __half2 h0 = __floats2half2_rn(a.x, a.y), h1 = __floats2half2_rn(a.z, a.w);
    __half2 h2 = __floats2half2_rn(b.x, b.y), h3 = __floats2half2_rn(b.z, b.w);
    uint4 o;
    o.x = *(uint32_t*)&h0; o.y = *(uint32_t*)&h1;
    o.z = *(uint32_t*)&h2; o.w = *(uint32_t*)&h3;
    *(uint4*)(d + i) = o;
}

// ---------------------------------------------------------------------------
extern "C" void kernel_launch(void* const* d_in, const int* in_sizes, int n_in,
                              void* d_out, int out_size)
{
    const float* x  = (const float*)d_in[0];
    const float* Wq = (const float*)d_in[1];
    const float* bq = (const float*)d_in[2];
    const float* Wk = (const float*)d_in[3];
    const float* bk = (const float*)d_in[4];
    const float* Wv = (const float*)d_in[5];
    const float* bv = (const float*)d_in[6];
    const float* Wo = (const float*)d_in[7];
    const float* bo = (const float*)d_in[8];
    float* out = (float*)d_out;

    __half *xh, *Wh, *Qh, *Kh, *Vh, *AOh;
    cudaGetSymbolAddress((void**)&xh,  g_xh);
    cudaGetSymbolAddress((void**)&Wh,  g_Wh);
    cudaGetSymbolAddress((void**)&Qh,  g_Qh);
    cudaGetSymbolAddress((void**)&Kh,  g_Kh);
    cudaGetSymbolAddress((void**)&Vh,  g_Vh);
    cudaGetSymbolAddress((void**)&AOh, g_AOh);

    const size_t WN = (size_t)Dn * Dn;   // 1M

    // fp32 -> fp16 conversions
    f32_to_f16<<<(unsigned)((size_t)Mn * Dn / 8 / 256), 256>>>(x,  xh);
    f32_to_f16<<<(unsigned)(WN / 8 / 256), 256>>>(Wq, Wh + 0 * WN);
    f32_to_f16<<<(unsigned)(WN / 8 / 256), 256>>>(Wk, Wh + 1 * WN);
    f32_to_f16<<<(unsigned)(WN / 8 / 256), 256>>>(Wv, Wh + 2 * WN);
    f32_to_f16<<<(unsigned)(WN / 8 / 256), 256>>>(Wo, Wh + 3 * WN);

    dim3 gproj(Dn / 128, Mn / 128);   // (8, 32)

    // QKV projections (fp16 out)
    proj_h<<<gproj, 256>>>(xh, Wh + 0 * WN, bq, Qh);
    proj_h<<<gproj, 256>>>(xh, Wh + 1 * WN, bk, Kh);
    proj_h<<<gproj, 256>>>(xh, Wh + 2 * WN, bv, Vh);

    // V transpose for AV B-operand
    dim3 gtr(Sn / 64, Dn / 64, Bn);
    transpose_v<<<gtr, 256>>>();

    // Scores (fp32 out)
    dim3 gs(Sn / 128, Sn / 128, Bn * Hn);
    scores_h<<<gs, 256>>>();

    // Softmax over head axis: fp32 -> fp16 probs
    const size_t tot = (size_t)Bn * Sn * Sn;   // 8388608
    softmax_h16<<<(unsigned)(tot / 256), 256>>>();

    // attn @ V
    dim3 gav(Sn / 128, 1, Bn * Hn);
    av_h<<<gav, 256>>>();

    // Output projection (fp32 out)
    proj_f<<<gproj, 256>>>(AOh, Wh + 3 * WN, bo, out);
}